// round 12
// baseline (speedup 1.0000x reference)
#include <cuda_runtime.h>
#include <cuda_bf16.h>
#include <cstdint>

#define NN 50000
#define EE 800000
#define DD 128
#define LL 3

// ---------------- scratch (device globals: no allocation allowed) ----------------
__device__ int    g_deg[NN];
__device__ int    g_off[NN + 1];
__device__ int    g_cur[NN];
__device__ int    g_eid[EE];
__device__ __align__(16) float  g_Hagg[(size_t)NN * DD];
__device__ __align__(16) float  g_H1[(size_t)NN * DD];
__device__ __align__(16) float  g_H2[(size_t)NN * DD];
__device__ double g_bn[12 * DD];          // per layer: sum1, sq1, sum2, sq2

// ---------------- bf16 split helpers ----------------
__device__ __forceinline__ void bfsplit2(float a0, float a1, uint32_t& hp, uint32_t& lp) {
    __nv_bfloat16 h0 = __float2bfloat16_rn(a0);
    __nv_bfloat16 h1 = __float2bfloat16_rn(a1);
    float r0 = a0 - __bfloat162float(h0);
    float r1 = a1 - __bfloat162float(h1);
    __nv_bfloat16 l0 = __float2bfloat16_rn(r0);
    __nv_bfloat16 l1 = __float2bfloat16_rn(r1);
    hp = ((uint32_t)__bfloat16_as_ushort(h1) << 16) | (uint32_t)__bfloat16_as_ushort(h0);
    lp = ((uint32_t)__bfloat16_as_ushort(l1) << 16) | (uint32_t)__bfloat16_as_ushort(l0);
}

#define MMA_BF16(d, a, b)                                                     \
    asm volatile(                                                             \
        "mma.sync.aligned.m16n8k16.row.col.f32.bf16.bf16.f32 "                \
        "{%0,%1,%2,%3},{%4,%5,%6,%7},{%8,%9},{%0,%1,%2,%3};"                  \
        : "+f"((d)[0]), "+f"((d)[1]), "+f"((d)[2]), "+f"((d)[3])              \
        : "r"((a)[0]), "r"((a)[1]), "r"((a)[2]), "r"((a)[3]),                 \
          "r"((b)[0]), "r"((b)[1]))

#define RED_GID(v)                                    \
    v += __shfl_xor_sync(0xffffffffu, v, 4);          \
    v += __shfl_xor_sync(0xffffffffu, v, 8);          \
    v += __shfl_xor_sync(0xffffffffu, v, 16);

__device__ __forceinline__ void bn_coef(const double* __restrict__ bsum,
                                        const double* __restrict__ bsq,
                                        const float* __restrict__ gm,
                                        const float* __restrict__ bt,
                                        int d, float& s, float& b) {
    double m = bsum[d] / (double)NN;
    double v = bsq[d] / (double)NN - m * m;
    s = gm[d] * rsqrtf((float)v + 1e-5f);
    b = bt[d] - (float)m * s;
}

// ---------------- CSR build ----------------
__global__ void hist_k(const int* __restrict__ dst, int* __restrict__ deg) {
    int i = blockIdx.x * blockDim.x + threadIdx.x;
    int st = gridDim.x * blockDim.x;
    for (int e = i; e < EE; e += st) atomicAdd(&deg[dst[e]], 1);
}

__global__ void scan_k(const int* __restrict__ deg, int* __restrict__ off,
                       int* __restrict__ cur, double* __restrict__ bn) {
    __shared__ int part[1024];
    int t = threadIdx.x;
    for (int i = t; i < 12 * DD; i += 1024) bn[i] = 0.0;
    const int CH = (NN + 1023) / 1024;
    int s = t * CH;
    int e = min(s + CH, NN);
    int acc = 0;
    for (int i = s; i < e; i++) acc += deg[i];
    part[t] = acc;
    __syncthreads();
    for (int d = 1; d < 1024; d <<= 1) {
        int v = (t >= d) ? part[t - d] : 0;
        __syncthreads();
        part[t] += v;
        __syncthreads();
    }
    int run = (t == 0) ? 0 : part[t - 1];
    for (int i = s; i < e; i++) { off[i] = run; cur[i] = run; run += deg[i]; }
    if (t == 1023) off[NN] = part[1023];
}

__global__ void scat_k(const int* __restrict__ dst, int* __restrict__ cur,
                       int* __restrict__ eid) {
    int i = blockIdx.x * blockDim.x + threadIdx.x;
    int st = gridDim.x * blockDim.x;
    for (int e = i; e < EE; e += st) {
        int p = atomicAdd(&cur[dst[e]], 1);
        eid[p] = e;
    }
}

// ---------------- aggregation v3: warp-per-node, shfl-batched indices, 4-edge unroll ----
__global__ void __launch_bounds__(256) agg_k(
    const float* __restrict__ X, const double* __restrict__ bsum,
    const double* __restrict__ bsq, const float* __restrict__ gm,
    const float* __restrict__ bt, int relu_in,
    const int* __restrict__ src, const float* __restrict__ ea,
    const int* __restrict__ off, const int* __restrict__ eid,
    float* __restrict__ out) {
    __shared__ float ssc[DD], ssh[DD];
    int tid = threadIdx.x;
    if (tid < DD) {
        float s = 1.0f, b = 0.0f;
        if (bsum) bn_coef(bsum, bsq, gm, bt, tid, s, b);
        ssc[tid] = s;
        ssh[tid] = b;
    }
    __syncthreads();

    int warp = (blockIdx.x * blockDim.x + tid) >> 5;
    if (warp >= NN) return;
    int lane = tid & 31;
    int d0 = lane * 4;
    int row = warp;

    float4 s4 = *(const float4*)&ssc[d0];
    float4 b4 = *(const float4*)&ssh[d0];

    float4 v = *(const float4*)&X[(size_t)row * DD + d0];
    float4 acc;
    acc.x = v.x * s4.x + b4.x;
    acc.y = v.y * s4.y + b4.y;
    acc.z = v.z * s4.z + b4.z;
    acc.w = v.w * s4.w + b4.w;
    if (relu_in) {
        acc.x = fmaxf(acc.x, 0.0f); acc.y = fmaxf(acc.y, 0.0f);
        acc.z = fmaxf(acc.z, 0.0f); acc.w = fmaxf(acc.w, 0.0f);
    }

    int i0 = off[row], i1 = off[row + 1];
    int nE = i1 - i0;

#define EDGE_ACC(xx, aa)                                                      \
    {                                                                         \
        float tx = xx.x * s4.x + b4.x, ty = xx.y * s4.y + b4.y;               \
        float tz = xx.z * s4.z + b4.z, tw = xx.w * s4.w + b4.w;               \
        if (relu_in) {                                                        \
            tx = fmaxf(tx, 0.f); ty = fmaxf(ty, 0.f);                         \
            tz = fmaxf(tz, 0.f); tw = fmaxf(tw, 0.f);                         \
        }                                                                     \
        acc.x += fmaxf(tx + aa.x, 0.f);                                       \
        acc.y += fmaxf(ty + aa.y, 0.f);                                       \
        acc.z += fmaxf(tz + aa.z, 0.f);                                       \
        acc.w += fmaxf(tw + aa.w, 0.f);                                       \
    }

    for (int base = 0; base < nE; base += 32) {
        // batch-load 32 edge ids + src ids (1 coalesced LDG + 1 L2 gather per lane)
        int rel = base + lane;
        int e_l = 0, s_l = 0;
        if (rel < nE) {
            e_l = eid[i0 + rel];
            s_l = src[e_l];
        }
        int cnt = min(32, nE - base);
        int j = 0;
        for (; j + 3 < cnt; j += 4) {
            int e0 = __shfl_sync(0xffffffffu, e_l, j);
            int e1 = __shfl_sync(0xffffffffu, e_l, j + 1);
            int e2 = __shfl_sync(0xffffffffu, e_l, j + 2);
            int e3 = __shfl_sync(0xffffffffu, e_l, j + 3);
            int n0 = __shfl_sync(0xffffffffu, s_l, j);
            int n1 = __shfl_sync(0xffffffffu, s_l, j + 1);
            int n2 = __shfl_sync(0xffffffffu, s_l, j + 2);
            int n3 = __shfl_sync(0xffffffffu, s_l, j + 3);
            float4 x0 = *(const float4*)&X[(size_t)n0 * DD + d0];
            float4 x1 = *(const float4*)&X[(size_t)n1 * DD + d0];
            float4 x2 = *(const float4*)&X[(size_t)n2 * DD + d0];
            float4 x3 = *(const float4*)&X[(size_t)n3 * DD + d0];
            float4 a0 = *(const float4*)&ea[(size_t)e0 * DD + d0];
            float4 a1 = *(const float4*)&ea[(size_t)e1 * DD + d0];
            float4 a2 = *(const float4*)&ea[(size_t)e2 * DD + d0];
            float4 a3 = *(const float4*)&ea[(size_t)e3 * DD + d0];
            EDGE_ACC(x0, a0) EDGE_ACC(x1, a1) EDGE_ACC(x2, a2) EDGE_ACC(x3, a3)
        }
        for (; j < cnt; j++) {
            int e0 = __shfl_sync(0xffffffffu, e_l, j);
            int n0 = __shfl_sync(0xffffffffu, s_l, j);
            float4 x0 = *(const float4*)&X[(size_t)n0 * DD + d0];
            float4 a0 = *(const float4*)&ea[(size_t)e0 * DD + d0];
            EDGE_ACC(x0, a0)
        }
    }
#undef EDGE_ACC
    *(float4*)&out[(size_t)row * DD + d0] = acc;
}

// ---------------- tensor-core GEMM (bf16x3, m16n8k16, resident B, pipelined A) --------
#define AST 12
#define BST 68
#define ABUFW (128 * AST)
#define GEMM_SMEM ((2 * 128 * BST + 4 * ABUFW + 5 * 128) * 4)   // 96768 B -> 2 CTA/SM

template <int FUSE>
__global__ void __launch_bounds__(256) gemm_tc(
    const float* __restrict__ A, const float* __restrict__ W,
    const float* __restrict__ bias,
    const double* __restrict__ bsum, const double* __restrict__ bsq,
    const float* __restrict__ gm, const float* __restrict__ bt,
    float* __restrict__ out,
    double* __restrict__ csum, double* __restrict__ csq, int M) {
    extern __shared__ float smem[];
    uint32_t* BsH = (uint32_t*)smem;
    uint32_t* BsL = BsH + 128 * BST;
    uint32_t* AsH = BsL + 128 * BST;          // 2 buffers
    uint32_t* AsL = AsH + 2 * ABUFW;
    float* bb  = (float*)(AsL + 2 * ABUFW);
    float* fsc = bb + 128;
    float* fsh = fsc + 128;
    float* cs  = fsh + 128;
    float* cq  = cs + 128;

    int tid = threadIdx.x;
    int lane = tid & 31, wid = tid >> 5;
    int wm = wid >> 1, wn = wid & 1;
    int gid = lane >> 2, tig = lane & 3;
    int m0 = blockIdx.x * 128;

    if (tid < 128) {
        bb[tid] = bias[tid];
        cs[tid] = 0.0f;
        cq[tid] = 0.0f;
        if (FUSE) {
            float s, b;
            bn_coef(bsum, bsq, gm, bt, tid, s, b);
            fsc[tid] = s;
            fsh[tid] = b;
        }
    }

    // load + bf16-split full B (128k x 128n) once per block, packed k-pairs
#pragma unroll
    for (int i = tid; i < 128 * 64; i += 256) {
        int kp = i >> 7;          // k-pair 0..63
        int n  = i & 127;
        float w0 = W[(size_t)(2 * kp) * DD + n];
        float w1 = W[(size_t)(2 * kp + 1) * DD + n];
        uint32_t hp, lp;
        bfsplit2(w0, w1, hp, lp);
        BsH[n * BST + kp] = hp;
        BsL[n * BST + kp] = lp;
    }

    int ar = tid >> 1;                 // A row 0..127
    int acf = (tid & 1) << 3;          // k float offset 0 or 8
    int acp = (tid & 1) << 2;          // k pair offset 0 or 4
    float4 pa0, pa1;
    {
        float4 z = make_float4(0.f, 0.f, 0.f, 0.f);
        pa0 = z; pa1 = z;
        if (m0 + ar < M) {
            pa0 = *(const float4*)&A[(size_t)(m0 + ar) * DD + acf];
            pa1 = *(const float4*)&A[(size_t)(m0 + ar) * DD + acf + 4];
        }
    }

    float accm[2][8][4];
#pragma unroll
    for (int mt = 0; mt < 2; mt++)
#pragma unroll
        for (int nt = 0; nt < 8; nt++)
#pragma unroll
            for (int r = 0; r < 4; r++) accm[mt][nt][r] = 0.0f;

    __syncthreads();   // fsc/fsh + B ready before chunk-0 A store

    {
        float vv[8] = {pa0.x, pa0.y, pa0.z, pa0.w, pa1.x, pa1.y, pa1.z, pa1.w};
        uint32_t* dh = &AsH[ar * AST + acp];
        uint32_t* dl = &AsL[ar * AST + acp];
#pragma unroll
        for (int j = 0; j < 4; j++) {
            float a0 = vv[2 * j], a1 = vv[2 * j + 1];
            if (FUSE) {
                int k = acf + 2 * j;
                a0 = fmaxf(a0 * fsc[k] + fsh[k], 0.0f);
                a1 = fmaxf(a1 * fsc[k + 1] + fsh[k + 1], 0.0f);
            }
            uint32_t hp, lp;
            bfsplit2(a0, a1, hp, lp);
            dh[j] = hp;
            dl[j] = lp;
        }
    }
    __syncthreads();

    for (int ch = 0; ch < 8; ch++) {
        int kc = ch * 16;
        if (ch < 7) {
            float4 z = make_float4(0.f, 0.f, 0.f, 0.f);
            pa0 = z; pa1 = z;
            if (m0 + ar < M) {
                pa0 = *(const float4*)&A[(size_t)(m0 + ar) * DD + kc + 16 + acf];
                pa1 = *(const float4*)&A[(size_t)(m0 + ar) * DD + kc + 16 + acf + 4];
            }
        }
        const uint32_t* AH = &AsH[(ch & 1) * ABUFW];
        const uint32_t* AL = &AsL[(ch & 1) * ABUFW];
        int kpg = ch * 8;

        uint32_t aH[2][4], aL[2][4], bH[8][2], bL[8][2];
#pragma unroll
        for (int mt = 0; mt < 2; mt++) {
            int r0 = wm * 32 + mt * 16 + gid;
            aH[mt][0] = AH[r0 * AST + tig];
            aH[mt][1] = AH[(r0 + 8) * AST + tig];
            aH[mt][2] = AH[r0 * AST + 4 + tig];
            aH[mt][3] = AH[(r0 + 8) * AST + 4 + tig];
            aL[mt][0] = AL[r0 * AST + tig];
            aL[mt][1] = AL[(r0 + 8) * AST + tig];
            aL[mt][2] = AL[r0 * AST + 4 + tig];
            aL[mt][3] = AL[(r0 + 8) * AST + 4 + tig];
        }
#pragma unroll
        for (int nt = 0; nt < 8; nt++) {
            int c = wn * 64 + nt * 8 + gid;
            bH[nt][0] = BsH[c * BST + kpg + tig];
            bH[nt][1] = BsH[c * BST + kpg + 4 + tig];
            bL[nt][0] = BsL[c * BST + kpg + tig];
            bL[nt][1] = BsL[c * BST + kpg + 4 + tig];
        }
#pragma unroll
        for (int mt = 0; mt < 2; mt++)
#pragma unroll
            for (int nt = 0; nt < 8; nt++) {
                MMA_BF16(accm[mt][nt], aH[mt], bH[nt]);
                MMA_BF16(accm[mt][nt], aH[mt], bL[nt]);
                MMA_BF16(accm[mt][nt], aL[mt], bH[nt]);
            }

        if (ch < 7) {
            int kn = kc + 16;
            float vv[8] = {pa0.x, pa0.y, pa0.z, pa0.w, pa1.x, pa1.y, pa1.z, pa1.w};
            uint32_t* dh = &AsH[((ch + 1) & 1) * ABUFW + ar * AST + acp];
            uint32_t* dl = &AsL[((ch + 1) & 1) * ABUFW + ar * AST + acp];
#pragma unroll
            for (int j = 0; j < 4; j++) {
                float a0 = vv[2 * j], a1 = vv[2 * j + 1];
                if (FUSE) {
                    int k = kn + acf + 2 * j;
                    a0 = fmaxf(a0 * fsc[k] + fsh[k], 0.0f);
                    a1 = fmaxf(a1 * fsc[k + 1] + fsh[k + 1], 0.0f);
                }
                uint32_t hp, lp;
                bfsplit2(a0, a1, hp, lp);
                dh[j] = hp;
                dl[j] = lp;
            }
        }
        __syncthreads();
    }

    // epilogue: bias add, store, fused column sums
#pragma unroll
    for (int nt = 0; nt < 8; nt++) {
        int c = wn * 64 + nt * 8 + tig * 2;
        float b0v = bb[c], b1v = bb[c + 1];
        float s0 = 0.f, s1 = 0.f, q0 = 0.f, q1 = 0.f;
#pragma unroll
        for (int mt = 0; mt < 2; mt++) {
            int r0 = m0 + wm * 32 + mt * 16 + gid;
            int r1 = r0 + 8;
            float v0 = accm[mt][nt][0] + b0v;
            float v1 = accm[mt][nt][1] + b1v;
            float v2 = accm[mt][nt][2] + b0v;
            float v3 = accm[mt][nt][3] + b1v;
            if (r0 < M) {
                *(float2*)&out[(size_t)r0 * DD + c] = make_float2(v0, v1);
                s0 += v0; s1 += v1; q0 += v0 * v0; q1 += v1 * v1;
            }
            if (r1 < M) {
                *(float2*)&out[(size_t)r1 * DD + c] = make_float2(v2, v3);
                s0 += v2; s1 += v3; q0 += v2 * v2; q1 += v3 * v3;
            }
        }
        RED_GID(s0); RED_GID(s1); RED_GID(q0); RED_GID(q1);
        if (gid == 0) {
            atomicAdd(&cs[c], s0);
            atomicAdd(&cs[c + 1], s1);
            atomicAdd(&cq[c], q0);
            atomicAdd(&cq[c + 1], q1);
        }
    }
    __syncthreads();
    if (tid < 128) {
        atomicAdd(&csum[tid], (double)cs[tid]);
        atomicAdd(&csq[tid], (double)cq[tid]);
    }
}

// ---------------- final BN apply (no relu) to d_out ----------------
__global__ void apply_k(const float* __restrict__ H, const double* __restrict__ bsum,
                        const double* __restrict__ bsq, const float* __restrict__ gm,
                        const float* __restrict__ bt, float* __restrict__ out) {
    __shared__ float ssc[DD], ssh[DD];
    int tid = threadIdx.x;
    if (tid < DD) {
        float s, b;
        bn_coef(bsum, bsq, gm, bt, tid, s, b);
        ssc[tid] = s;
        ssh[tid] = b;
    }
    __syncthreads();
    int i = blockIdx.x * blockDim.x + tid;
    int total = NN * DD / 4;
    if (i < total) {
        float4 h = ((const float4*)H)[i];
        int d = (i * 4) & (DD - 1);
        float4 o;
        o.x = h.x * ssc[d + 0] + ssh[d + 0];
        o.y = h.y * ssc[d + 1] + ssh[d + 1];
        o.z = h.z * ssc[d + 2] + ssh[d + 2];
        o.w = h.w * ssc[d + 3] + ssh[d + 3];
        ((float4*)out)[i] = o;
    }
}

// ---------------- launch ----------------
extern "C" void kernel_launch(void* const* d_in, const int* in_sizes, int n_in,
                              void* d_out, int out_size) {
    const float* x   = (const float*)d_in[0];
    const int*   ei  = (const int*)d_in[1];     // int32
    const float* ea  = (const float*)d_in[2];
    const float* W1  = (const float*)d_in[4];
    const float* b1  = (const float*)d_in[5];
    const float* gmm = (const float*)d_in[6];
    const float* bmm = (const float*)d_in[7];
    const float* W2  = (const float*)d_in[8];
    const float* b2  = (const float*)d_in[9];
    const float* go  = (const float*)d_in[10];
    const float* bo  = (const float*)d_in[11];
    float*       out = (float*)d_out;

    const int* src = ei;
    const int* dst = ei + EE;

    int *deg, *off, *cur, *eid;
    float *Hagg, *H1, *H2;
    double* bn;
    cudaGetSymbolAddress((void**)&deg, g_deg);
    cudaGetSymbolAddress((void**)&off, g_off);
    cudaGetSymbolAddress((void**)&cur, g_cur);
    cudaGetSymbolAddress((void**)&eid, g_eid);
    cudaGetSymbolAddress((void**)&Hagg, g_Hagg);
    cudaGetSymbolAddress((void**)&H1, g_H1);
    cudaGetSymbolAddress((void**)&H2, g_H2);
    cudaGetSymbolAddress((void**)&bn, g_bn);

    static int attr_done = 0;
    if (!attr_done) {
        cudaFuncSetAttribute(gemm_tc<0>, cudaFuncAttributeMaxDynamicSharedMemorySize, GEMM_SMEM);
        cudaFuncSetAttribute(gemm_tc<1>, cudaFuncAttributeMaxDynamicSharedMemorySize, GEMM_SMEM);
        attr_done = 1;
    }

    cudaMemsetAsync(deg, 0, NN * sizeof(int), 0);
    hist_k<<<1024, 256>>>(dst, deg);
    scan_k<<<1, 1024>>>(deg, off, cur, bn);
    scat_k<<<1024, 256>>>(dst, cur, eid);

    int MB = (NN + 127) / 128;
    int AGG_BLOCKS = (NN * 32 + 255) / 256;
    for (int i = 0; i < LL; i++) {
        const float* Xin = (i == 0) ? x : H2;
        double* bni = bn + (size_t)i * 4 * DD;
        const double* bprev = (i == 0) ? nullptr : bn + (size_t)(i - 1) * 4 * DD + 2 * DD;
        const float* gprev = (i == 0) ? go : go + (i - 1) * DD;
        const float* bprevf = (i == 0) ? bo : bo + (i - 1) * DD;
        agg_k<<<AGG_BLOCKS, 256>>>(Xin, bprev, bprev ? bprev + DD : nullptr,
                                   gprev, bprevf, (i > 0) ? 1 : 0, src, ea, off, eid, Hagg);
        gemm_tc<0><<<MB, 256, GEMM_SMEM>>>(Hagg, W1 + (size_t)i * DD * DD, b1 + i * DD,
                                           nullptr, nullptr, nullptr, nullptr,
                                           H1, bni, bni + DD, NN);
        gemm_tc<1><<<MB, 256, GEMM_SMEM>>>(H1, W2 + (size_t)i * DD * DD, b2 + i * DD,
                                           bni, bni + DD, gmm + i * DD, bmm + i * DD,
                                           H2, bni + 2 * DD, bni + 3 * DD, NN);
    }
    apply_k<<<(NN * DD / 4 + 255) / 256, 256>>>(H2, bn + 2 * 4 * DD + 2 * DD,
                                                bn + 2 * 4 * DD + 3 * DD,
                                                go + 2 * DD, bo + 2 * DD, out);
}

// round 13
// speedup vs baseline: 1.1001x; 1.1001x over previous
#include <cuda_runtime.h>
#include <cuda_bf16.h>
#include <cstdint>

#define NN 50000
#define EE 800000
#define DD 128
#define LL 3

// ---------------- scratch (device globals: no allocation allowed) ----------------
__device__ int    g_deg[NN];
__device__ int    g_off[NN + 1];
__device__ int    g_cur[NN];
__device__ int    g_eid[EE];
__device__ __align__(16) float  g_Hagg[(size_t)NN * DD];
__device__ __align__(16) float  g_H1[(size_t)NN * DD];
__device__ __align__(16) float  g_H2[(size_t)NN * DD];
__device__ double g_bn[12 * DD];          // per layer: sum1, sq1, sum2, sq2

// ---------------- bf16 split helpers ----------------
__device__ __forceinline__ void bfsplit2(float a0, float a1, uint32_t& hp, uint32_t& lp) {
    __nv_bfloat16 h0 = __float2bfloat16_rn(a0);
    __nv_bfloat16 h1 = __float2bfloat16_rn(a1);
    float r0 = a0 - __bfloat162float(h0);
    float r1 = a1 - __bfloat162float(h1);
    __nv_bfloat16 l0 = __float2bfloat16_rn(r0);
    __nv_bfloat16 l1 = __float2bfloat16_rn(r1);
    hp = ((uint32_t)__bfloat16_as_ushort(h1) << 16) | (uint32_t)__bfloat16_as_ushort(h0);
    lp = ((uint32_t)__bfloat16_as_ushort(l1) << 16) | (uint32_t)__bfloat16_as_ushort(l0);
}

#define MMA_BF16(d, a, b)                                                     \
    asm volatile(                                                             \
        "mma.sync.aligned.m16n8k16.row.col.f32.bf16.bf16.f32 "                \
        "{%0,%1,%2,%3},{%4,%5,%6,%7},{%8,%9},{%0,%1,%2,%3};"                  \
        : "+f"((d)[0]), "+f"((d)[1]), "+f"((d)[2]), "+f"((d)[3])              \
        : "r"((a)[0]), "r"((a)[1]), "r"((a)[2]), "r"((a)[3]),                 \
          "r"((b)[0]), "r"((b)[1]))

#define RED_GID(v)                                    \
    v += __shfl_xor_sync(0xffffffffu, v, 4);          \
    v += __shfl_xor_sync(0xffffffffu, v, 8);          \
    v += __shfl_xor_sync(0xffffffffu, v, 16);

__device__ __forceinline__ void bn_coef(const double* __restrict__ bsum,
                                        const double* __restrict__ bsq,
                                        const float* __restrict__ gm,
                                        const float* __restrict__ bt,
                                        int d, float& s, float& b) {
    double m = bsum[d] / (double)NN;
    double v = bsq[d] / (double)NN - m * m;
    s = gm[d] * rsqrtf((float)v + 1e-5f);
    b = bt[d] - (float)m * s;
}

// ---------------- CSR build ----------------
__global__ void hist_k(const int* __restrict__ dst, int* __restrict__ deg) {
    int i = blockIdx.x * blockDim.x + threadIdx.x;
    int st = gridDim.x * blockDim.x;
    for (int e = i; e < EE; e += st) atomicAdd(&deg[dst[e]], 1);
}

__global__ void scan_k(const int* __restrict__ deg, int* __restrict__ off,
                       int* __restrict__ cur, double* __restrict__ bn) {
    __shared__ int part[1024];
    int t = threadIdx.x;
    for (int i = t; i < 12 * DD; i += 1024) bn[i] = 0.0;
    const int CH = (NN + 1023) / 1024;
    int s = t * CH;
    int e = min(s + CH, NN);
    int acc = 0;
    for (int i = s; i < e; i++) acc += deg[i];
    part[t] = acc;
    __syncthreads();
    for (int d = 1; d < 1024; d <<= 1) {
        int v = (t >= d) ? part[t - d] : 0;
        __syncthreads();
        part[t] += v;
        __syncthreads();
    }
    int run = (t == 0) ? 0 : part[t - 1];
    for (int i = s; i < e; i++) { off[i] = run; cur[i] = run; run += deg[i]; }
    if (t == 1023) off[NN] = part[1023];
}

__global__ void scat_k(const int* __restrict__ dst, int* __restrict__ cur,
                       int* __restrict__ eid) {
    int i = blockIdx.x * blockDim.x + threadIdx.x;
    int st = gridDim.x * blockDim.x;
    for (int e = i; e < EE; e += st) {
        int p = atomicAdd(&cur[dst[e]], 1);
        eid[p] = e;
    }
}

// ---------------- aggregation (R11-proven form; ea loads streamed evict-first) ----------
__global__ void __launch_bounds__(256) agg_k(
    const float* __restrict__ X, const double* __restrict__ bsum,
    const double* __restrict__ bsq, const float* __restrict__ gm,
    const float* __restrict__ bt, int relu_in,
    const int* __restrict__ src, const float* __restrict__ ea,
    const int* __restrict__ off, const int* __restrict__ eid,
    float* __restrict__ out) {
    __shared__ float ssc[DD], ssh[DD];
    int tid = threadIdx.x;
    if (tid < DD) {
        float s = 1.0f, b = 0.0f;
        if (bsum) bn_coef(bsum, bsq, gm, bt, tid, s, b);
        ssc[tid] = s;
        ssh[tid] = b;
    }
    __syncthreads();

    int warp = (blockIdx.x * blockDim.x + tid) >> 5;
    if (warp >= NN) return;
    int lane = tid & 31;
    int d0 = lane * 4;
    int row = warp;

    float4 s4 = *(const float4*)&ssc[d0];
    float4 b4 = *(const float4*)&ssh[d0];

    float4 v = *(const float4*)&X[(size_t)row * DD + d0];
    float4 acc;
    acc.x = v.x * s4.x + b4.x;
    acc.y = v.y * s4.y + b4.y;
    acc.z = v.z * s4.z + b4.z;
    acc.w = v.w * s4.w + b4.w;
    if (relu_in) {
        acc.x = fmaxf(acc.x, 0.0f); acc.y = fmaxf(acc.y, 0.0f);
        acc.z = fmaxf(acc.z, 0.0f); acc.w = fmaxf(acc.w, 0.0f);
    }

    int i0 = off[row], i1 = off[row + 1];
    int i = i0;
#define EDGE_ACC(xx, aa)                                                      \
    {                                                                         \
        float tx = xx.x * s4.x + b4.x, ty = xx.y * s4.y + b4.y;               \
        float tz = xx.z * s4.z + b4.z, tw = xx.w * s4.w + b4.w;               \
        if (relu_in) {                                                        \
            tx = fmaxf(tx, 0.f); ty = fmaxf(ty, 0.f);                         \
            tz = fmaxf(tz, 0.f); tw = fmaxf(tw, 0.f);                         \
        }                                                                     \
        acc.x += fmaxf(tx + aa.x, 0.f);                                       \
        acc.y += fmaxf(ty + aa.y, 0.f);                                       \
        acc.z += fmaxf(tz + aa.z, 0.f);                                       \
        acc.w += fmaxf(tw + aa.w, 0.f);                                       \
    }
    for (; i + 1 < i1; i += 2) {
        int e0 = eid[i], e1 = eid[i + 1];
        int n0 = src[e0], n1 = src[e1];
        float4 x0 = *(const float4*)&X[(size_t)n0 * DD + d0];
        float4 x1 = *(const float4*)&X[(size_t)n1 * DD + d0];
        float4 a0 = __ldcs((const float4*)&ea[(size_t)e0 * DD + d0]);
        float4 a1 = __ldcs((const float4*)&ea[(size_t)e1 * DD + d0]);
        EDGE_ACC(x0, a0) EDGE_ACC(x1, a1)
    }
    if (i < i1) {
        int e0 = eid[i];
        int n0 = src[e0];
        float4 x0 = *(const float4*)&X[(size_t)n0 * DD + d0];
        float4 a0 = __ldcs((const float4*)&ea[(size_t)e0 * DD + d0]);
        EDGE_ACC(x0, a0)
    }
#undef EDGE_ACC
    *(float4*)&out[(size_t)row * DD + d0] = acc;
}

// ---------------- tensor-core GEMM (bf16x3, m16n8k16, resident B, pipelined A) --------
#define AST 12
#define BST 68
#define ABUFW (128 * AST)
#define GEMM_SMEM ((2 * 128 * BST + 4 * ABUFW + 5 * 128) * 4)   // 96768 B -> 2 CTA/SM

template <int FUSE>
__global__ void __launch_bounds__(256) gemm_tc(
    const float* __restrict__ A, const float* __restrict__ W,
    const float* __restrict__ bias,
    const double* __restrict__ bsum, const double* __restrict__ bsq,
    const float* __restrict__ gm, const float* __restrict__ bt,
    float* __restrict__ out,
    double* __restrict__ csum, double* __restrict__ csq, int M) {
    extern __shared__ float smem[];
    uint32_t* BsH = (uint32_t*)smem;
    uint32_t* BsL = BsH + 128 * BST;
    uint32_t* AsH = BsL + 128 * BST;          // 2 buffers
    uint32_t* AsL = AsH + 2 * ABUFW;
    float* bb  = (float*)(AsL + 2 * ABUFW);
    float* fsc = bb + 128;
    float* fsh = fsc + 128;
    float* cs  = fsh + 128;
    float* cq  = cs + 128;

    int tid = threadIdx.x;
    int lane = tid & 31, wid = tid >> 5;
    int wm = wid >> 1, wn = wid & 1;
    int gid = lane >> 2, tig = lane & 3;
    int m0 = blockIdx.x * 128;

    if (tid < 128) {
        bb[tid] = bias[tid];
        cs[tid] = 0.0f;
        cq[tid] = 0.0f;
        if (FUSE) {
            float s, b;
            bn_coef(bsum, bsq, gm, bt, tid, s, b);
            fsc[tid] = s;
            fsh[tid] = b;
        }
    }

    // load + bf16-split full B (128k x 128n) once per block, packed k-pairs
#pragma unroll
    for (int i = tid; i < 128 * 64; i += 256) {
        int kp = i >> 7;          // k-pair 0..63
        int n  = i & 127;
        float w0 = W[(size_t)(2 * kp) * DD + n];
        float w1 = W[(size_t)(2 * kp + 1) * DD + n];
        uint32_t hp, lp;
        bfsplit2(w0, w1, hp, lp);
        BsH[n * BST + kp] = hp;
        BsL[n * BST + kp] = lp;
    }

    int ar = tid >> 1;                 // A row 0..127
    int acf = (tid & 1) << 3;          // k float offset 0 or 8
    int acp = (tid & 1) << 2;          // k pair offset 0 or 4
    float4 pa0, pa1;
    {
        float4 z = make_float4(0.f, 0.f, 0.f, 0.f);
        pa0 = z; pa1 = z;
        if (m0 + ar < M) {
            pa0 = *(const float4*)&A[(size_t)(m0 + ar) * DD + acf];
            pa1 = *(const float4*)&A[(size_t)(m0 + ar) * DD + acf + 4];
        }
    }

    float accm[2][8][4];
#pragma unroll
    for (int mt = 0; mt < 2; mt++)
#pragma unroll
        for (int nt = 0; nt < 8; nt++)
#pragma unroll
            for (int r = 0; r < 4; r++) accm[mt][nt][r] = 0.0f;

    __syncthreads();   // fsc/fsh + B ready before chunk-0 A store

    {
        float vv[8] = {pa0.x, pa0.y, pa0.z, pa0.w, pa1.x, pa1.y, pa1.z, pa1.w};
        uint32_t* dh = &AsH[ar * AST + acp];
        uint32_t* dl = &AsL[ar * AST + acp];
#pragma unroll
        for (int j = 0; j < 4; j++) {
            float a0 = vv[2 * j], a1 = vv[2 * j + 1];
            if (FUSE) {
                int k = acf + 2 * j;
                a0 = fmaxf(a0 * fsc[k] + fsh[k], 0.0f);
                a1 = fmaxf(a1 * fsc[k + 1] + fsh[k + 1], 0.0f);
            }
            uint32_t hp, lp;
            bfsplit2(a0, a1, hp, lp);
            dh[j] = hp;
            dl[j] = lp;
        }
    }
    __syncthreads();

    for (int ch = 0; ch < 8; ch++) {
        int kc = ch * 16;
        if (ch < 7) {
            float4 z = make_float4(0.f, 0.f, 0.f, 0.f);
            pa0 = z; pa1 = z;
            if (m0 + ar < M) {
                pa0 = *(const float4*)&A[(size_t)(m0 + ar) * DD + kc + 16 + acf];
                pa1 = *(const float4*)&A[(size_t)(m0 + ar) * DD + kc + 16 + acf + 4];
            }
        }
        const uint32_t* AH = &AsH[(ch & 1) * ABUFW];
        const uint32_t* AL = &AsL[(ch & 1) * ABUFW];
        int kpg = ch * 8;

        uint32_t aH[2][4], aL[2][4], bH[8][2], bL[8][2];
#pragma unroll
        for (int mt = 0; mt < 2; mt++) {
            int r0 = wm * 32 + mt * 16 + gid;
            aH[mt][0] = AH[r0 * AST + tig];
            aH[mt][1] = AH[(r0 + 8) * AST + tig];
            aH[mt][2] = AH[r0 * AST + 4 + tig];
            aH[mt][3] = AH[(r0 + 8) * AST + 4 + tig];
            aL[mt][0] = AL[r0 * AST + tig];
            aL[mt][1] = AL[(r0 + 8) * AST + tig];
            aL[mt][2] = AL[r0 * AST + 4 + tig];
            aL[mt][3] = AL[(r0 + 8) * AST + 4 + tig];
        }
#pragma unroll
        for (int nt = 0; nt < 8; nt++) {
            int c = wn * 64 + nt * 8 + gid;
            bH[nt][0] = BsH[c * BST + kpg + tig];
            bH[nt][1] = BsH[c * BST + kpg + 4 + tig];
            bL[nt][0] = BsL[c * BST + kpg + tig];
            bL[nt][1] = BsL[c * BST + kpg + 4 + tig];
        }
#pragma unroll
        for (int mt = 0; mt < 2; mt++)
#pragma unroll
            for (int nt = 0; nt < 8; nt++) {
                MMA_BF16(accm[mt][nt], aH[mt], bH[nt]);
                MMA_BF16(accm[mt][nt], aH[mt], bL[nt]);
                MMA_BF16(accm[mt][nt], aL[mt], bH[nt]);
            }

        if (ch < 7) {
            int kn = kc + 16;
            float vv[8] = {pa0.x, pa0.y, pa0.z, pa0.w, pa1.x, pa1.y, pa1.z, pa1.w};
            uint32_t* dh = &AsH[((ch + 1) & 1) * ABUFW + ar * AST + acp];
            uint32_t* dl = &AsL[((ch + 1) & 1) * ABUFW + ar * AST + acp];
#pragma unroll
            for (int j = 0; j < 4; j++) {
                float a0 = vv[2 * j], a1 = vv[2 * j + 1];
                if (FUSE) {
                    int k = kn + acf + 2 * j;
                    a0 = fmaxf(a0 * fsc[k] + fsh[k], 0.0f);
                    a1 = fmaxf(a1 * fsc[k + 1] + fsh[k + 1], 0.0f);
                }
                uint32_t hp, lp;
                bfsplit2(a0, a1, hp, lp);
                dh[j] = hp;
                dl[j] = lp;
            }
        }
        __syncthreads();
    }

    // epilogue: bias add, store, fused column sums
#pragma unroll
    for (int nt = 0; nt < 8; nt++) {
        int c = wn * 64 + nt * 8 + tig * 2;
        float b0v = bb[c], b1v = bb[c + 1];
        float s0 = 0.f, s1 = 0.f, q0 = 0.f, q1 = 0.f;
#pragma unroll
        for (int mt = 0; mt < 2; mt++) {
            int r0 = m0 + wm * 32 + mt * 16 + gid;
            int r1 = r0 + 8;
            float v0 = accm[mt][nt][0] + b0v;
            float v1 = accm[mt][nt][1] + b1v;
            float v2 = accm[mt][nt][2] + b0v;
            float v3 = accm[mt][nt][3] + b1v;
            if (r0 < M) {
                *(float2*)&out[(size_t)r0 * DD + c] = make_float2(v0, v1);
                s0 += v0; s1 += v1; q0 += v0 * v0; q1 += v1 * v1;
            }
            if (r1 < M) {
                *(float2*)&out[(size_t)r1 * DD + c] = make_float2(v2, v3);
                s0 += v2; s1 += v3; q0 += v2 * v2; q1 += v3 * v3;
            }
        }
        RED_GID(s0); RED_GID(s1); RED_GID(q0); RED_GID(q1);
        if (gid == 0) {
            atomicAdd(&cs[c], s0);
            atomicAdd(&cs[c + 1], s1);
            atomicAdd(&cq[c], q0);
            atomicAdd(&cq[c + 1], q1);
        }
    }
    __syncthreads();
    if (tid < 128) {
        atomicAdd(&csum[tid], (double)cs[tid]);
        atomicAdd(&csq[tid], (double)cq[tid]);
    }
}

// ---------------- final BN apply (no relu) to d_out ----------------
__global__ void apply_k(const float* __restrict__ H, const double* __restrict__ bsum,
                        const double* __restrict__ bsq, const float* __restrict__ gm,
                        const float* __restrict__ bt, float* __restrict__ out) {
    __shared__ float ssc[DD], ssh[DD];
    int tid = threadIdx.x;
    if (tid < DD) {
        float s, b;
        bn_coef(bsum, bsq, gm, bt, tid, s, b);
        ssc[tid] = s;
        ssh[tid] = b;
    }
    __syncthreads();
    int i = blockIdx.x * blockDim.x + tid;
    int total = NN * DD / 4;
    if (i < total) {
        float4 h = ((const float4*)H)[i];
        int d = (i * 4) & (DD - 1);
        float4 o;
        o.x = h.x * ssc[d + 0] + ssh[d + 0];
        o.y = h.y * ssc[d + 1] + ssh[d + 1];
        o.z = h.z * ssc[d + 2] + ssh[d + 2];
        o.w = h.w * ssc[d + 3] + ssh[d + 3];
        ((float4*)out)[i] = o;
    }
}

// ---------------- launch ----------------
extern "C" void kernel_launch(void* const* d_in, const int* in_sizes, int n_in,
                              void* d_out, int out_size) {
    const float* x   = (const float*)d_in[0];
    const int*   ei  = (const int*)d_in[1];     // int32
    const float* ea  = (const float*)d_in[2];
    const float* W1  = (const float*)d_in[4];
    const float* b1  = (const float*)d_in[5];
    const float* gmm = (const float*)d_in[6];
    const float* bmm = (const float*)d_in[7];
    const float* W2  = (const float*)d_in[8];
    const float* b2  = (const float*)d_in[9];
    const float* go  = (const float*)d_in[10];
    const float* bo  = (const float*)d_in[11];
    float*       out = (float*)d_out;

    const int* src = ei;
    const int* dst = ei + EE;

    int *deg, *off, *cur, *eid;
    float *Hagg, *H1, *H2;
    double* bn;
    cudaGetSymbolAddress((void**)&deg, g_deg);
    cudaGetSymbolAddress((void**)&off, g_off);
    cudaGetSymbolAddress((void**)&cur, g_cur);
    cudaGetSymbolAddress((void**)&eid, g_eid);
    cudaGetSymbolAddress((void**)&Hagg, g_Hagg);
    cudaGetSymbolAddress((void**)&H1, g_H1);
    cudaGetSymbolAddress((void**)&H2, g_H2);
    cudaGetSymbolAddress((void**)&bn, g_bn);

    static int attr_done = 0;
    if (!attr_done) {
        cudaFuncSetAttribute(gemm_tc<0>, cudaFuncAttributeMaxDynamicSharedMemorySize, GEMM_SMEM);
        cudaFuncSetAttribute(gemm_tc<1>, cudaFuncAttributeMaxDynamicSharedMemorySize, GEMM_SMEM);
        attr_done = 1;
    }

    cudaMemsetAsync(deg, 0, NN * sizeof(int), 0);
    hist_k<<<1024, 256>>>(dst, deg);
    scan_k<<<1, 1024>>>(deg, off, cur, bn);
    scat_k<<<1024, 256>>>(dst, cur, eid);

    int MB = (NN + 127) / 128;
    int AGG_BLOCKS = (NN * 32 + 255) / 256;
    for (int i = 0; i < LL; i++) {
        const float* Xin = (i == 0) ? x : H2;
        double* bni = bn + (size_t)i * 4 * DD;
        const double* bprev = (i == 0) ? nullptr : bn + (size_t)(i - 1) * 4 * DD + 2 * DD;
        const float* gprev = (i == 0) ? go : go + (i - 1) * DD;
        const float* bprevf = (i == 0) ? bo : bo + (i - 1) * DD;
        agg_k<<<AGG_BLOCKS, 256>>>(Xin, bprev, bprev ? bprev + DD : nullptr,
                                   gprev, bprevf, (i > 0) ? 1 : 0, src, ea, off, eid, Hagg);
        gemm_tc<0><<<MB, 256, GEMM_SMEM>>>(Hagg, W1 + (size_t)i * DD * DD, b1 + i * DD,
                                           nullptr, nullptr, nullptr, nullptr,
                                           H1, bni, bni + DD, NN);
        gemm_tc<1><<<MB, 256, GEMM_SMEM>>>(H1, W2 + (size_t)i * DD * DD, b2 + i * DD,
                                           bni, bni + DD, gmm + i * DD, bmm + i * DD,
                                           H2, bni + 2 * DD, bni + 3 * DD, NN);
    }
    apply_k<<<(NN * DD / 4 + 255) / 256, 256>>>(H2, bn + 2 * 4 * DD + 2 * DD,
                                                bn + 2 * 4 * DD + 3 * DD,
                                                go + 2 * DD, bo + 2 * DD, out);
}